// round 11
// baseline (speedup 1.0000x reference)
#include <cuda_runtime.h>
#include <cuda_bf16.h>
#include <cstdint>

// ======================= problem constants =======================
#define MDIM 8192
#define KDIM 4096
#define NDIM 4096

// ======================= hybrid GEMM tiling =======================
constexpr int BM = 128;             // CTA M tile
constexpr int BN = 256;             // CTA N tile: [0,160) HMMA, [160,256) dp4a
constexpr int NH = 160;             // HMMA N region
constexpr int BK = 64;              // K elems per stage
constexpr int STAGES = 4;
constexpr int KITERS = KDIM / BK;   // 64
// per-stage smem: A_bf16 16K | B_bf16 20K | A_i8 8K | B_i8 6K
constexpr int OFF_BBF = 16384;
constexpr int OFF_AI8 = 36864;
constexpr int OFF_BI8 = 45056;
constexpr int STAGE_BYTES = 51200;                // 50 KB
constexpr int SMEM_TOTAL = STAGES * STAGE_BYTES;  // 200 KB

// ======================= device scratch (no allocs allowed) =======================
__device__ __align__(1024) __nv_bfloat16 g_xb[(size_t)MDIM * KDIM]; // 64 MB
__device__ __align__(1024) __nv_bfloat16 g_wb[(size_t)NDIM * KDIM]; // 32 MB
__device__ __align__(1024) int8_t g_xq[(size_t)MDIM * KDIM];        // 32 MB
__device__ __align__(1024) int8_t g_wq[(size_t)NDIM * KDIM];        // 16 MB
__device__ unsigned int g_maxbits;
__device__ int g_swapsb;

// ======================= helpers =======================
__device__ __forceinline__ uint32_t smem_u32(const void* p) {
    uint32_t a;
    asm("{ .reg .u64 t; cvta.to.shared.u64 t, %1; cvt.u32.u64 %0, t; }"
        : "=r"(a) : "l"(p));
    return a;
}

__device__ __forceinline__ void cp16(uint32_t dst, const void* src) {
    asm volatile("cp.async.cg.shared.global [%0], [%1], 16;" :: "r"(dst), "l"(src));
}

__device__ __forceinline__ uint32_t lds32(uint32_t addr) {
    uint32_t v;
    asm volatile("ld.shared.b32 %0, [%1];" : "=r"(v) : "r"(addr));
    return v;
}

__device__ __forceinline__ void ldsm4(uint32_t& r0, uint32_t& r1, uint32_t& r2,
                                      uint32_t& r3, uint32_t addr) {
    asm volatile("ldmatrix.sync.aligned.m8n8.x4.shared.b16 {%0,%1,%2,%3}, [%4];"
                 : "=r"(r0), "=r"(r1), "=r"(r2), "=r"(r3) : "r"(addr));
}

__device__ __forceinline__ void mma_bf16(float* c, const uint32_t* a,
                                         uint32_t b0, uint32_t b1) {
    asm volatile(
        "mma.sync.aligned.m16n8k16.row.col.f32.bf16.bf16.f32 "
        "{%0,%1,%2,%3}, {%4,%5,%6,%7}, {%8,%9}, {%0,%1,%2,%3};"
        : "+f"(c[0]), "+f"(c[1]), "+f"(c[2]), "+f"(c[3])
        : "r"(a[0]), "r"(a[1]), "r"(a[2]), "r"(a[3]), "r"(b0), "r"(b1));
}

__device__ __forceinline__ void mma_s8(int* c, const uint32_t* a, uint32_t b0,
                                       uint32_t b1) {
    asm volatile(
        "mma.sync.aligned.m16n8k32.row.col.s32.s8.s8.s32 "
        "{%0,%1,%2,%3}, {%4,%5,%6,%7}, {%8,%9}, {%0,%1,%2,%3};"
        : "+r"(c[0]), "+r"(c[1]), "+r"(c[2]), "+r"(c[3])
        : "r"(a[0]), "r"(a[1]), "r"(a[2]), "r"(a[3]), "r"(b0), "r"(b1));
}

// ======================= preprocessing =======================
__global__ void k_detect(const float* __restrict__ cand_sw) {
    if (threadIdx.x == 0) g_maxbits = 0u;
    bool neg = false;
    for (int i = threadIdx.x; i < 256; i += 32) neg |= (cand_sw[i] < 0.0f);
    unsigned b = __ballot_sync(0xffffffffu, neg);
    if (threadIdx.x == 0) g_swapsb = (b != 0u);
}

__global__ void k_maxabs(const float4* __restrict__ x, int n4) {
    unsigned int m = 0;
    for (int i = blockIdx.x * blockDim.x + threadIdx.x; i < n4;
         i += gridDim.x * blockDim.x) {
        float4 v = x[i];
        m = max(m, __float_as_uint(fabsf(v.x)));
        m = max(m, __float_as_uint(fabsf(v.y)));
        m = max(m, __float_as_uint(fabsf(v.z)));
        m = max(m, __float_as_uint(fabsf(v.w)));
    }
    #pragma unroll
    for (int o = 16; o > 0; o >>= 1)
        m = max(m, __shfl_xor_sync(0xffffffffu, m, o));
    if ((threadIdx.x & 31) == 0) atomicMax(&g_maxbits, m);
}

// x -> int8-valued bf16 AND packed int8 (both exact round-half-even).
__global__ void k_quant(const float4* __restrict__ x) {
    int i = blockIdx.x * blockDim.x + threadIdx.x;
    float sx = __fdiv_rn(__uint_as_float(g_maxbits), 127.0f);
    float4 v = x[i];
    float q0 = fminf(fmaxf(rintf(__fdiv_rn(v.x, sx)), -127.f), 127.f);
    float q1 = fminf(fmaxf(rintf(__fdiv_rn(v.y, sx)), -127.f), 127.f);
    float q2 = fminf(fmaxf(rintf(__fdiv_rn(v.z, sx)), -127.f), 127.f);
    float q3 = fminf(fmaxf(rintf(__fdiv_rn(v.w, sx)), -127.f), 127.f);
    __nv_bfloat162 p0, p1;
    p0.x = __float2bfloat16(q0); p0.y = __float2bfloat16(q1);
    p1.x = __float2bfloat16(q2); p1.y = __float2bfloat16(q3);
    uint2 o;
    o.x = *reinterpret_cast<unsigned int*>(&p0);
    o.y = *reinterpret_cast<unsigned int*>(&p1);
    reinterpret_cast<uint2*>(g_xb)[i] = o;
    int i0 = (int)q0, i1 = (int)q1, i2 = (int)q2, i3 = (int)q3;
    unsigned int u = (i0 & 0xFF) | ((i1 & 0xFF) << 8) | ((i2 & 0xFF) << 16) |
                     ((unsigned)(i3 & 0xFF) << 24);
    reinterpret_cast<unsigned int*>(g_xq)[i] = u;
}

// w_q int32 words -> bf16 AND packed int8.
__global__ void k_wpack(const int4* __restrict__ w) {
    int i = blockIdx.x * blockDim.x + threadIdx.x;  // one int4 = 4 weights
    int4 p = w[i];
    __nv_bfloat162 h0, h1;
    h0.x = __float2bfloat16((float)p.x); h0.y = __float2bfloat16((float)p.y);
    h1.x = __float2bfloat16((float)p.z); h1.y = __float2bfloat16((float)p.w);
    uint2 o;
    o.x = *reinterpret_cast<unsigned int*>(&h0);
    o.y = *reinterpret_cast<unsigned int*>(&h1);
    reinterpret_cast<uint2*>(g_wb)[i] = o;
    unsigned int u = (p.x & 0xFF) | ((p.y & 0xFF) << 8) | ((p.z & 0xFF) << 16) |
                     ((unsigned)(p.w & 0xFF) << 24);
    reinterpret_cast<unsigned int*>(g_wq)[i] = u;
}

// ======================= hybrid dual-pipe GEMM =======================
__global__ void __launch_bounds__(256, 1)
k_gemm(const float* __restrict__ p_sw, const float* __restrict__ p_bias,
       float* __restrict__ C) {
    extern __shared__ char smem[];
    const uint32_t sb = smem_u32(smem);
    const int tid = threadIdx.x;
    const int lane = tid & 31;
    const int wid = tid >> 5;
    const int g = lane >> 2;        // fragment row group 0..7
    const int tg = lane & 3;        // thread-in-group 0..3
    const int q = lane >> 3;        // ldmatrix quad 0..3
    const int l = lane & 7;         // lane-in-quad

    const int m0 = blockIdx.y * BM;
    const int n0 = blockIdx.x * BN;

    // ---- async fill of one stage: all 4 tiles ----
    const int a_row = tid >> 1;          // 0..127
    const int a_c0 = (tid & 1) * 4;      // 0 or 4
    const char* AgB = (const char*)(g_xb + (size_t)(m0 + a_row) * KDIM);
    const char* WbB = (const char*)(g_wb + (size_t)n0 * KDIM);
    const char* AqB = (const char*)(g_xq + (size_t)m0 * KDIM);
    const char* WqB = (const char*)(g_wq + (size_t)(n0 + NH) * KDIM);

    auto fill = [&](int stage, int j) {
        const uint32_t base = sb + stage * STAGE_BYTES;
        const int kb2 = j * 128;  // bf16 bytes per k-iter
        const int kb1 = j * 64;   // int8 bytes per k-iter
        // A bf16: 128 rows x 8 chunks (1024), 4/thread
        #pragma unroll
        for (int i = 0; i < 4; i++) {
            int c16 = a_c0 + i;
            cp16(base + a_row * 128 + ((c16 ^ (a_row & 7)) << 4),
                 AgB + kb2 + c16 * 16);
        }
        // B bf16: 160 rows x 8 chunks (1280), 5/thread
        #pragma unroll
        for (int i = 0; i < 5; i++) {
            int ch = tid + 256 * i;
            int row = ch >> 3, c16 = ch & 7;
            cp16(base + OFF_BBF + row * 128 + ((c16 ^ (row & 7)) << 4),
                 WbB + (size_t)row * (KDIM * 2) + kb2 + c16 * 16);
        }
        // A int8: 128 rows x 4 chunks (512), 2/thread
        #pragma unroll
        for (int i = 0; i < 2; i++) {
            int ch = tid + 256 * i;
            int row = ch >> 2, c16 = ch & 3;
            cp16(base + OFF_AI8 + row * 64 + ((c16 ^ (row & 3)) << 4),
                 AqB + (size_t)row * KDIM + kb1 + c16 * 16);
        }
        // B int8: 96 rows x 4 chunks (384), <=2/thread
        #pragma unroll
        for (int i = 0; i < 2; i++) {
            int ch = tid + 256 * i;
            if (ch < 384) {
                int row = ch >> 2, c16 = ch & 3;
                cp16(base + OFF_BI8 + row * 64 + ((c16 ^ (row & 3)) << 4),
                     WqB + (size_t)row * KDIM + kb1 + c16 * 16);
            }
        }
    };

    // role split: warps 0-3 HMMA (one per SMSP), warps 4-7 dp4a (one per SMSP)
    const bool is_hmma = wid < 4;
    const int wm = is_hmma ? ((wid >> 1) * 64) : (((wid - 4) >> 1) * 64);
    const int wnh = (wid & 1) * 80;        // HMMA warp N offset in [0,160)
    const int wnd = ((wid - 4) & 1) * 48;  // dp4a warp N offset in [0,96)

    const int arow_base = (q & 1) * 8 + l;
    const int ac_sel = q >> 1;
    const int brow_base = (q >> 1) * 8 + l;
    const int bc_sel = q & 1;

    float acch[4][10][4];
    int accd[4][6][4];
    if (is_hmma) {
        #pragma unroll
        for (int mt = 0; mt < 4; mt++)
            #pragma unroll
            for (int nt = 0; nt < 10; nt++)
                #pragma unroll
                for (int r = 0; r < 4; r++) acch[mt][nt][r] = 0.0f;
    } else {
        #pragma unroll
        for (int mt = 0; mt < 4; mt++)
            #pragma unroll
            for (int nt = 0; nt < 6; nt++)
                #pragma unroll
                for (int r = 0; r < 4; r++) accd[mt][nt][r] = 0;
    }

    #pragma unroll
    for (int p = 0; p < STAGES - 1; p++) {
        fill(p, p);
        asm volatile("cp.async.commit_group;" ::: "memory");
    }

    for (int j = 0; j < KITERS; j++) {
        asm volatile("cp.async.wait_group %0;" :: "n"(STAGES - 2) : "memory");
        __syncthreads();
        if (j + STAGES - 1 < KITERS)
            fill((j + STAGES - 1) & (STAGES - 1), j + STAGES - 1);
        asm volatile("cp.async.commit_group;" ::: "memory");

        const uint32_t base = sb + (j & (STAGES - 1)) * STAGE_BYTES;

        if (is_hmma) {
            const uint32_t Ab = base;            // A bf16
            const uint32_t Bb = base + OFF_BBF;  // B bf16
            #pragma unroll
            for (int ks = 0; ks < 4; ks++) {
                uint32_t af[4][4];
                #pragma unroll
                for (int mt = 0; mt < 4; mt++) {
                    int row = wm + mt * 16 + arow_base;
                    int c = (2 * ks + ac_sel) ^ (row & 7);
                    ldsm4(af[mt][0], af[mt][1], af[mt][2], af[mt][3],
                          Ab + row * 128 + (c << 4));
                }
                uint32_t bfr[5][4];
                #pragma unroll
                for (int nb = 0; nb < 5; nb++) {
                    int nrow = wnh + nb * 16 + brow_base;
                    int c = (2 * ks + bc_sel) ^ (nrow & 7);
                    ldsm4(bfr[nb][0], bfr[nb][1], bfr[nb][2], bfr[nb][3],
                          Bb + nrow * 128 + (c << 4));
                }
                #pragma unroll
                for (int mt = 0; mt < 4; mt++)
                    #pragma unroll
                    for (int nb = 0; nb < 5; nb++) {
                        mma_bf16(acch[mt][2 * nb], af[mt], bfr[nb][0], bfr[nb][1]);
                        mma_bf16(acch[mt][2 * nb + 1], af[mt], bfr[nb][2], bfr[nb][3]);
                    }
            }
        } else {
            const uint32_t Ai = base + OFF_AI8;
            const uint32_t Bi = base + OFF_BI8;
            #pragma unroll
            for (int ks2 = 0; ks2 < 2; ks2++) {
                const int cLo = (2 * ks2) ^ (g & 3);
                const uint32_t offLo = ((uint32_t)cLo << 4) + tg * 4;
                const uint32_t offHi = offLo ^ 16;
                uint32_t af2[4][4];
                #pragma unroll
                for (int mt = 0; mt < 4; mt++) {
                    const uint32_t r0 = Ai + (wm + mt * 16 + g) * 64;
                    af2[mt][0] = lds32(r0 + offLo);
                    af2[mt][1] = lds32(r0 + 8 * 64 + offLo);
                    af2[mt][2] = lds32(r0 + offHi);
                    af2[mt][3] = lds32(r0 + 8 * 64 + offHi);
                }
                uint32_t bf2[6][2];
                #pragma unroll
                for (int nt = 0; nt < 6; nt++) {
                    const uint32_t r0 = Bi + (wnd + nt * 8 + g) * 64;
                    bf2[nt][0] = lds32(r0 + offLo);
                    bf2[nt][1] = lds32(r0 + offHi);
                }
                #pragma unroll
                for (int mt = 0; mt < 4; mt++)
                    #pragma unroll
                    for (int nt = 0; nt < 6; nt++)
                        mma_s8(accd[mt][nt], af2[mt], bf2[nt][0], bf2[nt][1]);
            }
        }
    }

    // ---- epilogue: y = acc * (s_x * s_w[n]) + bias[n] ----
    const float* s_w = g_swapsb ? p_bias : p_sw;
    const float* bias = g_swapsb ? p_sw : p_bias;
    const float sx = __fdiv_rn(__uint_as_float(g_maxbits), 127.0f);

    if (is_hmma) {
        #pragma unroll
        for (int nt = 0; nt < 10; nt++) {
            const int n = n0 + wnh + nt * 8 + 2 * tg;
            const float s0 = __fmul_rn(sx, __ldg(s_w + n));
            const float s1 = __fmul_rn(sx, __ldg(s_w + n + 1));
            const float b0 = __ldg(bias + n);
            const float b1 = __ldg(bias + n + 1);
            #pragma unroll
            for (int mt = 0; mt < 4; mt++) {
                const int m = m0 + wm + mt * 16 + g;
                float2 v0, v1;
                v0.x = __fadd_rn(__fmul_rn(acch[mt][nt][0], s0), b0);
                v0.y = __fadd_rn(__fmul_rn(acch[mt][nt][1], s1), b1);
                v1.x = __fadd_rn(__fmul_rn(acch[mt][nt][2], s0), b0);
                v1.y = __fadd_rn(__fmul_rn(acch[mt][nt][3], s1), b1);
                *reinterpret_cast<float2*>(C + (size_t)m * NDIM + n) = v0;
                *reinterpret_cast<float2*>(C + (size_t)(m + 8) * NDIM + n) = v1;
            }
        }
    } else {
        #pragma unroll
        for (int nt = 0; nt < 6; nt++) {
            const int n = n0 + NH + wnd + nt * 8 + 2 * tg;
            const float s0 = __fmul_rn(sx, __ldg(s_w + n));
            const float s1 = __fmul_rn(sx, __ldg(s_w + n + 1));
            const float b0 = __ldg(bias + n);
            const float b1 = __ldg(bias + n + 1);
            #pragma unroll
            for (int mt = 0; mt < 4; mt++) {
                const int m = m0 + wm + mt * 16 + g;
                float2 v0, v1;
                v0.x = __fadd_rn(__fmul_rn(__int2float_rn(accd[mt][nt][0]), s0), b0);
                v0.y = __fadd_rn(__fmul_rn(__int2float_rn(accd[mt][nt][1]), s1), b1);
                v1.x = __fadd_rn(__fmul_rn(__int2float_rn(accd[mt][nt][2]), s0), b0);
                v1.y = __fadd_rn(__fmul_rn(__int2float_rn(accd[mt][nt][3]), s1), b1);
                *reinterpret_cast<float2*>(C + (size_t)m * NDIM + n) = v0;
                *reinterpret_cast<float2*>(C + (size_t)(m + 8) * NDIM + n) = v1;
            }
        }
    }
}

// ======================= launch =======================
extern "C" void kernel_launch(void* const* d_in, const int* in_sizes, int n_in,
                              void* d_out, int out_size) {
    const float* x = nullptr;
    const int4* wq32 = nullptr;
    const float* small[2] = {nullptr, nullptr};
    int nsmall = 0;
    for (int i = 0; i < n_in; i++) {
        if (in_sizes[i] == MDIM * KDIM) x = (const float*)d_in[i];
        else if (in_sizes[i] == NDIM * KDIM) wq32 = (const int4*)d_in[i];
        else if (nsmall < 2) small[nsmall++] = (const float*)d_in[i];
    }
    const float* p_sw = small[0];
    const float* p_bias = small[1];
    float* out = (float*)d_out;

    k_detect<<<1, 32>>>(p_sw);
    k_maxabs<<<1184, 256>>>((const float4*)x, MDIM * KDIM / 4);
    k_quant<<<(MDIM * KDIM / 4) / 256, 256>>>((const float4*)x);
    k_wpack<<<(NDIM * KDIM / 4) / 256, 256>>>(wq32);

    cudaFuncSetAttribute(k_gemm, cudaFuncAttributeMaxDynamicSharedMemorySize,
                         SMEM_TOTAL);
    k_gemm<<<dim3(NDIM / BN, MDIM / BM), 256, SMEM_TOTAL>>>(p_sw, p_bias, out);
}

// round 12
// speedup vs baseline: 2.8156x; 2.8156x over previous
#include <cuda_runtime.h>
#include <cuda_bf16.h>
#include <cstdint>

// ======================= problem constants =======================
#define MDIM 8192
#define KDIM 4096
#define NDIM 4096

// ======================= bf16 GEMM tiling =======================
constexpr int BM = 128;             // CTA M tile
constexpr int BN = 256;             // CTA N tile
constexpr int BK = 64;              // K elems per stage (bf16) -> 128B rows
constexpr int STAGES = 4;
constexpr int KITERS = KDIM / BK;   // 64
constexpr int A_BYTES = BM * 128;   // 16 KB
constexpr int B_BYTES = BN * 128;   // 32 KB
constexpr int STAGE_BYTES = A_BYTES + B_BYTES;   // 48 KB
constexpr int SMEM_TOTAL = STAGES * STAGE_BYTES; // 192 KB
constexpr int NTHREADS = 512;       // 16 warps -> 4 per SMSP

// ======================= device scratch (no allocs allowed) =======================
__device__ __align__(1024) __nv_bfloat16 g_xb[(size_t)MDIM * KDIM]; // 64 MB
__device__ __align__(1024) __nv_bfloat16 g_wb[(size_t)NDIM * KDIM]; // 32 MB
__device__ unsigned int g_maxbits;
__device__ int g_swapsb;

// ======================= helpers =======================
__device__ __forceinline__ uint32_t smem_u32(const void* p) {
    uint32_t a;
    asm("{ .reg .u64 t; cvta.to.shared.u64 t, %1; cvt.u32.u64 %0, t; }"
        : "=r"(a) : "l"(p));
    return a;
}

__device__ __forceinline__ void cp16(uint32_t dst, const void* src) {
    asm volatile("cp.async.cg.shared.global [%0], [%1], 16;" :: "r"(dst), "l"(src));
}

__device__ __forceinline__ void ldsm4(uint32_t& r0, uint32_t& r1, uint32_t& r2,
                                      uint32_t& r3, uint32_t addr) {
    asm volatile("ldmatrix.sync.aligned.m8n8.x4.shared.b16 {%0,%1,%2,%3}, [%4];"
                 : "=r"(r0), "=r"(r1), "=r"(r2), "=r"(r3) : "r"(addr));
}

__device__ __forceinline__ void mma_bf16(float* c, const uint32_t* a,
                                         uint32_t b0, uint32_t b1) {
    asm volatile(
        "mma.sync.aligned.m16n8k16.row.col.f32.bf16.bf16.f32 "
        "{%0,%1,%2,%3}, {%4,%5,%6,%7}, {%8,%9}, {%0,%1,%2,%3};"
        : "+f"(c[0]), "+f"(c[1]), "+f"(c[2]), "+f"(c[3])
        : "r"(a[0]), "r"(a[1]), "r"(a[2]), "r"(a[3]), "r"(b0), "r"(b1));
}

// ======================= preprocessing =======================
// init + s_w/bias disambiguation in one launch (s_w strictly positive).
__global__ void k_detect(const float* __restrict__ cand_sw) {
    if (threadIdx.x == 0) g_maxbits = 0u;
    bool neg = false;
    for (int i = threadIdx.x; i < 256; i += 32) neg |= (cand_sw[i] < 0.0f);
    unsigned b = __ballot_sync(0xffffffffu, neg);
    if (threadIdx.x == 0) g_swapsb = (b != 0u);
}

__global__ void k_maxabs(const float4* __restrict__ x, int n4) {
    unsigned int m = 0;
    for (int i = blockIdx.x * blockDim.x + threadIdx.x; i < n4;
         i += gridDim.x * blockDim.x) {
        float4 v = x[i];
        m = max(m, __float_as_uint(fabsf(v.x)));
        m = max(m, __float_as_uint(fabsf(v.y)));
        m = max(m, __float_as_uint(fabsf(v.z)));
        m = max(m, __float_as_uint(fabsf(v.w)));
    }
    #pragma unroll
    for (int o = 16; o > 0; o >>= 1)
        m = max(m, __shfl_xor_sync(0xffffffffu, m, o));
    if ((threadIdx.x & 31) == 0) atomicMax(&g_maxbits, m);
}

// x -> int8-valued bf16, exact: round-half-even(x / s_x) clamped to [-127,127].
__global__ void k_quant(const float4* __restrict__ x) {
    int i = blockIdx.x * blockDim.x + threadIdx.x;
    float sx = __fdiv_rn(__uint_as_float(g_maxbits), 127.0f);
    float4 v = x[i];
    float q0 = fminf(fmaxf(rintf(__fdiv_rn(v.x, sx)), -127.f), 127.f);
    float q1 = fminf(fmaxf(rintf(__fdiv_rn(v.y, sx)), -127.f), 127.f);
    float q2 = fminf(fmaxf(rintf(__fdiv_rn(v.z, sx)), -127.f), 127.f);
    float q3 = fminf(fmaxf(rintf(__fdiv_rn(v.w, sx)), -127.f), 127.f);
    __nv_bfloat162 p0, p1;
    p0.x = __float2bfloat16(q0); p0.y = __float2bfloat16(q1);
    p1.x = __float2bfloat16(q2); p1.y = __float2bfloat16(q3);
    uint2 o;
    o.x = *reinterpret_cast<unsigned int*>(&p0);
    o.y = *reinterpret_cast<unsigned int*>(&p1);
    reinterpret_cast<uint2*>(g_xb)[i] = o;
}

// w_q int32 words -> bf16 (values in [-127,127], exact in bf16).
__global__ void k_wpack(const int4* __restrict__ w) {
    int i = blockIdx.x * blockDim.x + threadIdx.x;  // one int4 = 4 weights
    int4 p = w[i];
    __nv_bfloat162 h0, h1;
    h0.x = __float2bfloat16((float)p.x); h0.y = __float2bfloat16((float)p.y);
    h1.x = __float2bfloat16((float)p.z); h1.y = __float2bfloat16((float)p.w);
    uint2 o;
    o.x = *reinterpret_cast<unsigned int*>(&h0);
    o.y = *reinterpret_cast<unsigned int*>(&h1);
    reinterpret_cast<uint2*>(g_wb)[i] = o;
}

// ======================= bf16 HMMA GEMM (16 warps, 4 per SMSP) =======================
__global__ void __launch_bounds__(NTHREADS, 1)
k_gemm(const float* __restrict__ p_sw, const float* __restrict__ p_bias,
       float* __restrict__ C) {
    extern __shared__ char smem[];
    const uint32_t sb = smem_u32(smem);
    const int tid = threadIdx.x;
    const int lane = tid & 31;
    const int wid = tid >> 5;       // 0..15
    const int g = lane >> 2;        // fragment row group 0..7
    const int tg = lane & 3;        // thread-in-group 0..3
    const int q = lane >> 3;        // ldmatrix quad 0..3
    const int l = lane & 7;         // lane-in-quad
    const int wm = (wid >> 3) * 64; // 2 warp rows along M (64 each)
    const int wn = (wid & 7) * 32;  // 8 warp cols along N (32 each)

    const int m0 = blockIdx.y * BM;
    const int n0 = blockIdx.x * BN;

    // ---- async fill (16B chunks, XOR-swizzled within 128B rows) ----
    const char* AgB = (const char*)(g_xb + (size_t)m0 * KDIM);
    const char* WbB = (const char*)(g_wb + (size_t)n0 * KDIM);

    auto fill = [&](int stage, int j) {
        const uint32_t sA = sb + stage * STAGE_BYTES;
        const uint32_t sB = sA + A_BYTES;
        const int kb = j * 128;  // bytes: BK elems * 2
        // A: 128 rows x 8 chunks = 1024, 2 per thread
        #pragma unroll
        for (int i = 0; i < 2; i++) {
            int ch = tid + NTHREADS * i;
            int row = ch >> 3, c16 = ch & 7;
            cp16(sA + row * 128 + ((c16 ^ (row & 7)) << 4),
                 AgB + (size_t)row * (KDIM * 2) + kb + c16 * 16);
        }
        // B: 256 rows x 8 chunks = 2048, 4 per thread
        #pragma unroll
        for (int i = 0; i < 4; i++) {
            int ch = tid + NTHREADS * i;
            int row = ch >> 3, c16 = ch & 7;
            cp16(sB + row * 128 + ((c16 ^ (row & 7)) << 4),
                 WbB + (size_t)row * (KDIM * 2) + kb + c16 * 16);
        }
    };

    // per-warp fragment base rows (ks-independent parts)
    const int arow_base = (q & 1) * 8 + l;
    const int ac_sel = q >> 1;
    const int brow_base = (q >> 1) * 8 + l;
    const int bc_sel = q & 1;

    float acc[4][4][4];
    #pragma unroll
    for (int mt = 0; mt < 4; mt++)
        #pragma unroll
        for (int nt = 0; nt < 4; nt++)
            #pragma unroll
            for (int r = 0; r < 4; r++) acc[mt][nt][r] = 0.0f;

    #pragma unroll
    for (int p = 0; p < STAGES - 1; p++) {
        fill(p, p);
        asm volatile("cp.async.commit_group;" ::: "memory");
    }

    for (int j = 0; j < KITERS; j++) {
        asm volatile("cp.async.wait_group %0;" :: "n"(STAGES - 2) : "memory");
        __syncthreads();
        if (j + STAGES - 1 < KITERS)
            fill((j + STAGES - 1) & (STAGES - 1), j + STAGES - 1);
        asm volatile("cp.async.commit_group;" ::: "memory");

        const uint32_t Ab = sb + (j & (STAGES - 1)) * STAGE_BYTES;
        const uint32_t Bb = Ab + A_BYTES;

        #pragma unroll
        for (int ks = 0; ks < 4; ks++) {
            uint32_t af[4][4];
            #pragma unroll
            for (int mt = 0; mt < 4; mt++) {
                int row = wm + mt * 16 + arow_base;
                int c = (2 * ks + ac_sel) ^ (row & 7);
                ldsm4(af[mt][0], af[mt][1], af[mt][2], af[mt][3],
                      Ab + row * 128 + (c << 4));
            }
            uint32_t bfr[2][4];
            #pragma unroll
            for (int nb = 0; nb < 2; nb++) {
                int nrow = wn + nb * 16 + brow_base;
                int c = (2 * ks + bc_sel) ^ (nrow & 7);
                ldsm4(bfr[nb][0], bfr[nb][1], bfr[nb][2], bfr[nb][3],
                      Bb + nrow * 128 + (c << 4));
            }
            #pragma unroll
            for (int mt = 0; mt < 4; mt++)
                #pragma unroll
                for (int nb = 0; nb < 2; nb++) {
                    mma_bf16(acc[mt][2 * nb], af[mt], bfr[nb][0], bfr[nb][1]);
                    mma_bf16(acc[mt][2 * nb + 1], af[mt], bfr[nb][2], bfr[nb][3]);
                }
        }
    }

    // ---- epilogue: y = acc * (s_x * s_w[n]) + bias[n] ----
    const float* s_w = g_swapsb ? p_bias : p_sw;
    const float* bias = g_swapsb ? p_sw : p_bias;
    const float sx = __fdiv_rn(__uint_as_float(g_maxbits), 127.0f);
    #pragma unroll
    for (int nt = 0; nt < 4; nt++) {
        const int n = n0 + wn + nt * 8 + 2 * tg;
        const float s0 = __fmul_rn(sx, __ldg(s_w + n));
        const float s1 = __fmul_rn(sx, __ldg(s_w + n + 1));
        const float b0 = __ldg(bias + n);
        const float b1 = __ldg(bias + n + 1);
        #pragma unroll
        for (int mt = 0; mt < 4; mt++) {
            const int m = m0 + wm + mt * 16 + g;
            float2 v0, v1;
            v0.x = __fadd_rn(__fmul_rn(acc[mt][nt][0], s0), b0);
            v0.y = __fadd_rn(__fmul_rn(acc[mt][nt][1], s1), b1);
            v1.x = __fadd_rn(__fmul_rn(acc[mt][nt][2], s0), b0);
            v1.y = __fadd_rn(__fmul_rn(acc[mt][nt][3], s1), b1);
            *reinterpret_cast<float2*>(C + (size_t)m * NDIM + n) = v0;
            *reinterpret_cast<float2*>(C + (size_t)(m + 8) * NDIM + n) = v1;
        }
    }
}

// ======================= launch =======================
extern "C" void kernel_launch(void* const* d_in, const int* in_sizes, int n_in,
                              void* d_out, int out_size) {
    const float* x = nullptr;
    const int4* wq32 = nullptr;
    const float* small[2] = {nullptr, nullptr};
    int nsmall = 0;
    for (int i = 0; i < n_in; i++) {
        if (in_sizes[i] == MDIM * KDIM) x = (const float*)d_in[i];
        else if (in_sizes[i] == NDIM * KDIM) wq32 = (const int4*)d_in[i];
        else if (nsmall < 2) small[nsmall++] = (const float*)d_in[i];
    }
    const float* p_sw = small[0];
    const float* p_bias = small[1];
    float* out = (float*)d_out;

    k_detect<<<1, 32>>>(p_sw);
    k_maxabs<<<1184, 256>>>((const float4*)x, MDIM * KDIM / 4);
    k_quant<<<(MDIM * KDIM / 4) / 256, 256>>>((const float4*)x);
    k_wpack<<<(NDIM * KDIM / 4) / 256, 256>>>(wq32);

    cudaFuncSetAttribute(k_gemm, cudaFuncAttributeMaxDynamicSharedMemorySize,
                         SMEM_TOTAL);
    k_gemm<<<dim3(NDIM / BN, MDIM / BM), NTHREADS, SMEM_TOTAL>>>(p_sw, p_bias, out);
}

// round 16
// speedup vs baseline: 2.9800x; 1.0584x over previous
#include <cuda_runtime.h>
#include <cuda_bf16.h>
#include <cstdint>

// ======================= problem constants =======================
#define MDIM 8192
#define KDIM 4096
#define NDIM 4096

// ======================= bf16 GEMM tiling =======================
constexpr int BM = 128;             // CTA M tile
constexpr int BN = 128;             // CTA N tile
constexpr int BK = 64;              // K elems per stage (bf16) -> 128B rows
constexpr int STAGES = 3;
constexpr int KITERS = KDIM / BK;   // 64
constexpr int A_BYTES = BM * 128;   // 16 KB
constexpr int B_BYTES = BN * 128;   // 16 KB
constexpr int STAGE_BYTES = A_BYTES + B_BYTES;   // 32 KB
constexpr int SMEM_TOTAL = STAGES * STAGE_BYTES; // 96 KB -> 2 CTAs/SM
constexpr int NTHREADS = 256;       // 8 warps; 2 CTAs/SM -> 4 warps/SMSP

// ======================= device scratch (no allocs allowed) =======================
__device__ __align__(1024) __nv_bfloat16 g_xb[(size_t)MDIM * KDIM]; // 64 MB
__device__ __align__(1024) __nv_bfloat16 g_wb[(size_t)NDIM * KDIM]; // 32 MB
__device__ unsigned int g_maxbits;
__device__ int g_swapsb;

// ======================= helpers =======================
__device__ __forceinline__ uint32_t smem_u32(const void* p) {
    uint32_t a;
    asm("{ .reg .u64 t; cvta.to.shared.u64 t, %1; cvt.u32.u64 %0, t; }"
        : "=r"(a) : "l"(p));
    return a;
}

__device__ __forceinline__ void cp16(uint32_t dst, const void* src) {
    asm volatile("cp.async.cg.shared.global [%0], [%1], 16;" :: "r"(dst), "l"(src));
}

__device__ __forceinline__ void ldsm4(uint32_t& r0, uint32_t& r1, uint32_t& r2,
                                      uint32_t& r3, uint32_t addr) {
    asm volatile("ldmatrix.sync.aligned.m8n8.x4.shared.b16 {%0,%1,%2,%3}, [%4];"
                 : "=r"(r0), "=r"(r1), "=r"(r2), "=r"(r3) : "r"(addr));
}

__device__ __forceinline__ void mma_bf16(float* c, const uint32_t* a,
                                         uint32_t b0, uint32_t b1) {
    asm volatile(
        "mma.sync.aligned.m16n8k16.row.col.f32.bf16.bf16.f32 "
        "{%0,%1,%2,%3}, {%4,%5,%6,%7}, {%8,%9}, {%0,%1,%2,%3};"
        : "+f"(c[0]), "+f"(c[1]), "+f"(c[2]), "+f"(c[3])
        : "r"(a[0]), "r"(a[1]), "r"(a[2]), "r"(a[3]), "r"(b0), "r"(b1));
}

// ======================= preprocessing =======================
// init + s_w/bias disambiguation in one launch (s_w strictly positive).
__global__ void k_detect(const float* __restrict__ cand_sw) {
    if (threadIdx.x == 0) g_maxbits = 0u;
    bool neg = false;
    for (int i = threadIdx.x; i < 256; i += 32) neg |= (cand_sw[i] < 0.0f);
    unsigned b = __ballot_sync(0xffffffffu, neg);
    if (threadIdx.x == 0) g_swapsb = (b != 0u);
}

__global__ void k_maxabs(const float4* __restrict__ x, int n4) {
    unsigned int m = 0;
    for (int i = blockIdx.x * blockDim.x + threadIdx.x; i < n4;
         i += gridDim.x * blockDim.x) {
        float4 v = x[i];
        m = max(m, __float_as_uint(fabsf(v.x)));
        m = max(m, __float_as_uint(fabsf(v.y)));
        m = max(m, __float_as_uint(fabsf(v.z)));
        m = max(m, __float_as_uint(fabsf(v.w)));
    }
    #pragma unroll
    for (int o = 16; o > 0; o >>= 1)
        m = max(m, __shfl_xor_sync(0xffffffffu, m, o));
    if ((threadIdx.x & 31) == 0) atomicMax(&g_maxbits, m);
}

// x -> int8-valued bf16, exact: round-half-even(x / s_x) clamped to [-127,127].
__global__ void k_quant(const float4* __restrict__ x) {
    int i = blockIdx.x * blockDim.x + threadIdx.x;
    float sx = __fdiv_rn(__uint_as_float(g_maxbits), 127.0f);
    float4 v = x[i];
    float q0 = fminf(fmaxf(rintf(__fdiv_rn(v.x, sx)), -127.f), 127.f);
    float q1 = fminf(fmaxf(rintf(__fdiv_rn(v.y, sx)), -127.f), 127.f);
    float q2 = fminf(fmaxf(rintf(__fdiv_rn(v.z, sx)), -127.f), 127.f);
    float q3 = fminf(fmaxf(rintf(__fdiv_rn(v.w, sx)), -127.f), 127.f);
    __nv_bfloat162 p0, p1;
    p0.x = __float2bfloat16(q0); p0.y = __float2bfloat16(q1);
    p1.x = __float2bfloat16(q2); p1.y = __float2bfloat16(q3);
    uint2 o;
    o.x = *reinterpret_cast<unsigned int*>(&p0);
    o.y = *reinterpret_cast<unsigned int*>(&p1);
    reinterpret_cast<uint2*>(g_xb)[i] = o;
}

// w_q int32 words -> bf16 (values in [-127,127], exact in bf16).
__global__ void k_wpack(const int4* __restrict__ w) {
    int i = blockIdx.x * blockDim.x + threadIdx.x;  // one int4 = 4 weights
    int4 p = w[i];
    __nv_bfloat162 h0, h1;
    h0.x = __float2bfloat16((float)p.x); h0.y = __float2bfloat16((float)p.y);
    h1.x = __float2bfloat16((float)p.z); h1.y = __float2bfloat16((float)p.w);
    uint2 o;
    o.x = *reinterpret_cast<unsigned int*>(&h0);
    o.y = *reinterpret_cast<unsigned int*>(&h1);
    reinterpret_cast<uint2*>(g_wb)[i] = o;
}

// ======================= bf16 HMMA GEMM (2 CTAs/SM, 8 warps each) =======================
__global__ void __launch_bounds__(NTHREADS, 2)
k_gemm(const float* __restrict__ p_sw, const float* __restrict__ p_bias,
       float* __restrict__ C) {
    extern __shared__ char smem[];
    const uint32_t sb = smem_u32(smem);
    const int tid = threadIdx.x;
    const int lane = tid & 31;
    const int wid = tid >> 5;       // 0..7
    const int g = lane >> 2;        // fragment row group 0..7
    const int tg = lane & 3;        // thread-in-group 0..3
    const int q = lane >> 3;        // ldmatrix quad 0..3
    const int l = lane & 7;         // lane-in-quad
    const int wm = (wid >> 2) * 64; // 2 warp rows along M (64 each)
    const int wn = (wid & 3) * 32;  // 4 warp cols along N (32 each)

    const int m0 = blockIdx.y * BM;
    const int n0 = blockIdx.x * BN;

    // ---- async fill (16B chunks, XOR-swizzled within 128B rows) ----
    const char* AgB = (const char*)(g_xb + (size_t)m0 * KDIM);
    const char* WbB = (const char*)(g_wb + (size_t)n0 * KDIM);

    auto fill = [&](int stage, int j) {
        const uint32_t sA = sb + stage * STAGE_BYTES;
        const uint32_t sB = sA + A_BYTES;
        const int kb = j * 128;  // bytes: BK elems * 2
        // A: 128 rows x 8 chunks = 1024, 4 per thread
        #pragma unroll
        for (int i = 0; i < 4; i++) {
            int ch = tid + NTHREADS * i;
            int row = ch >> 3, c16 = ch & 7;
            cp16(sA + row * 128 + ((c16 ^ (row & 7)) << 4),
                 AgB + (size_t)row * (KDIM * 2) + kb + c16 * 16);
        }
        // B: 128 rows x 8 chunks = 1024, 4 per thread
        #pragma unroll
        for (int i = 0; i < 4; i++) {
            int ch = tid + NTHREADS * i;
            int row = ch >> 3, c16 = ch & 7;
            cp16(sB + row * 128 + ((c16 ^ (row & 7)) << 4),
                 WbB + (size_t)row * (KDIM * 2) + kb + c16 * 16);
        }
    };

    // per-warp fragment base rows (ks-independent parts)
    const int arow_base = (q & 1) * 8 + l;
    const int ac_sel = q >> 1;
    const int brow_base = (q >> 1) * 8 + l;
    const int bc_sel = q & 1;

    float acc[4][4][4];
    #pragma unroll
    for (int mt = 0; mt < 4; mt++)
        #pragma unroll
        for (int nt = 0; nt < 4; nt++)
            #pragma unroll
            for (int r = 0; r < 4; r++) acc[mt][nt][r] = 0.0f;

    #pragma unroll
    for (int p = 0; p < STAGES - 1; p++) {
        fill(p, p);
        asm volatile("cp.async.commit_group;" ::: "memory");
    }

    int stage = 0;
    for (int j = 0; j < KITERS; j++) {
        asm volatile("cp.async.wait_group %0;" :: "n"(STAGES - 2) : "memory");
        __syncthreads();
        if (j + STAGES - 1 < KITERS) {
            int fs = stage + STAGES - 1;
            if (fs >= STAGES) fs -= STAGES;
            fill(fs, j + STAGES - 1);
        }
        asm volatile("cp.async.commit_group;" ::: "memory");

        const uint32_t Ab = sb + stage * STAGE_BYTES;
        const uint32_t Bb = Ab + A_BYTES;
        if (++stage == STAGES) stage = 0;

        #pragma unroll
        for (int ks = 0; ks < 4; ks++) {
            uint32_t af[4][4];
            #pragma unroll
            for (int mt = 0; mt < 4; mt++) {
                int row = wm + mt * 16 + arow_base;
                int c = (2 * ks + ac_sel) ^ (row & 7);
                ldsm4(af[mt][0], af[mt][1], af[mt][2], af[mt][3],
                      Ab + row * 128 + (c << 4));
            }
            uint32_t bfr[2][4];
            #pragma unroll
            for (int nb = 0; nb < 2; nb++) {
                int nrow = wn + nb * 16 + brow_base;
                int c = (2 * ks + bc_sel) ^ (nrow & 7);
                ldsm4(bfr[nb][0], bfr[nb][1], bfr[nb][2], bfr[nb][3],
                      Bb + nrow * 128 + (c << 4));
            }
            #pragma unroll
            for (int mt = 0; mt < 4; mt++)
                #pragma unroll
                for (int nb = 0; nb < 2; nb++) {
                    mma_bf16(acc[mt][2 * nb], af[mt], bfr[nb][0], bfr[nb][1]);
                    mma_bf16(acc[mt][2 * nb + 1], af[mt], bfr[nb][2], bfr[nb][3]);
                }
        }
    }

    // ---- epilogue: y = acc * (s_x * s_w[n]) + bias[n] ----
    const float* s_w = g_swapsb ? p_bias : p_sw;
    const float* bias = g_swapsb ? p_sw : p_bias;
    const float sx = __fdiv_rn(__uint_as_float(g_maxbits), 127.0f);
    #pragma unroll
    for (int nt = 0; nt < 4; nt++) {
        const int n = n0 + wn + nt * 8 + 2 * tg;
        const float s0 = __fmul_rn(sx, __ldg(s_w + n));
        const float s1 = __fmul_rn(sx, __ldg(s_w + n + 1));
        const float b0 = __ldg(bias + n);
        const float b1 = __ldg(bias + n + 1);
        #pragma unroll
        for (int mt = 0; mt < 4; mt++) {
            const int m = m0 + wm + mt * 16 + g;
            float2 v0, v1;
            v0.x = __fadd_rn(__fmul_rn(acc[mt][nt][0], s0), b0);
            v0.y = __fadd_rn(__fmul_rn(acc[mt][nt][1], s1), b1);
            v1.x = __fadd_rn(__fmul_rn(acc[mt][nt][2], s0), b0);
            v1.y = __fadd_rn(__fmul_rn(acc[mt][nt][3], s1), b1);
            *reinterpret_cast<float2*>(C + (size_t)m * NDIM + n) = v0;
            *reinterpret_cast<float2*>(C + (size_t)(m + 8) * NDIM + n) = v1;
        }
    }
}

// ======================= launch =======================
extern "C" void kernel_launch(void* const* d_in, const int* in_sizes, int n_in,
                              void* d_out, int out_size) {
    const float* x = nullptr;
    const int4* wq32 = nullptr;
    const float* small[2] = {nullptr, nullptr};
    int nsmall = 0;
    for (int i = 0; i < n_in; i++) {
        if (in_sizes[i] == MDIM * KDIM) x = (const float*)d_in[i];
        else if (in_sizes[i] == NDIM * KDIM) wq32 = (const int4*)d_in[i];
        else if (nsmall < 2) small[nsmall++] = (const float*)d_in[i];
    }
    const float* p_sw = small[0];
    const float* p_bias = small[1];
    float* out = (float*)d_out;

    k_detect<<<1, 32>>>(p_sw);
    k_maxabs<<<1184, 256>>>((const float4*)x, MDIM * KDIM / 4);
    k_quant<<<(MDIM * KDIM / 4) / 256, 256>>>((const float4*)x);
    k_wpack<<<(NDIM * KDIM / 4) / 256, 256>>>(wq32);

    cudaFuncSetAttribute(k_gemm, cudaFuncAttributeMaxDynamicSharedMemorySize,
                         SMEM_TOTAL);
    k_gemm<<<dim3(NDIM / BN, MDIM / BM), NTHREADS, SMEM_TOTAL>>>(p_sw, p_bias, out);
}